// round 1
// baseline (speedup 1.0000x reference)
#include <cuda_runtime.h>
#include <cstdint>

// Problem constants
constexpr int BATCH = 128;
constexpr int CCH   = 512;   // channels
constexpr int SS    = 1024;  // H*W tokens per sample
constexpr int NPER  = CCH * SS;        // 524288 elements per sample
constexpr float EPS = 1e-5f;

// Scratch (allocation-free rule: __device__ globals)
__device__ float g_mu[BATCH];
__device__ float g_rstd[BATCH];
__device__ float g_t[(size_t)BATCH * SS * CCH];    // tokens (B, S, C), C contiguous — 256 MB
__device__ float g_hdn[(size_t)BATCH * SS * CCH];  // hidden (B, S, C) — 256 MB

// ---------------------------------------------------------------------------
// Kernel 1: per-sample mean / rstd over 524288 elements. grid = B, block = 512.
// ---------------------------------------------------------------------------
__global__ void ln_stats_kernel(const float* __restrict__ x) {
    const int b = blockIdx.x;
    const float4* xb = reinterpret_cast<const float4*>(x + (size_t)b * NPER);
    const int n4 = NPER / 4;  // 131072

    float s = 0.f, sq = 0.f;
    for (int i = threadIdx.x; i < n4; i += blockDim.x) {
        float4 v = xb[i];
        s  += v.x + v.y + v.z + v.w;
        sq += v.x * v.x + v.y * v.y + v.z * v.z + v.w * v.w;
    }
    // warp reduce
    #pragma unroll
    for (int o = 16; o > 0; o >>= 1) {
        s  += __shfl_down_sync(0xffffffffu, s,  o);
        sq += __shfl_down_sync(0xffffffffu, sq, o);
    }
    __shared__ float shs[16], shq[16];
    const int wid = threadIdx.x >> 5, lane = threadIdx.x & 31;
    if (lane == 0) { shs[wid] = s; shq[wid] = sq; }
    __syncthreads();
    if (wid == 0) {
        const int nw = blockDim.x >> 5;
        s  = (lane < nw) ? shs[lane] : 0.f;
        sq = (lane < nw) ? shq[lane] : 0.f;
        #pragma unroll
        for (int o = 8; o > 0; o >>= 1) {
            s  += __shfl_down_sync(0xffffffffu, s,  o);
            sq += __shfl_down_sync(0xffffffffu, sq, o);
        }
        if (lane == 0) {
            float mu  = s / (float)NPER;
            float var = sq / (float)NPER - mu * mu;
            g_mu[b]   = mu;
            g_rstd[b] = rsqrtf(var + EPS);
        }
    }
}

// ---------------------------------------------------------------------------
// Kernel 2: normalize + transpose (B,C,S) -> tokens (B,S,C), both sides coalesced.
// grid = (S/32, C/32, B), block = (32, 8). 32x33 smem tile.
// ---------------------------------------------------------------------------
__global__ void ln_apply_kernel(const float* __restrict__ x,
                                const float* __restrict__ lnw,
                                const float* __restrict__ lnb) {
    __shared__ float tile[32][33];
    const int b  = blockIdx.z;
    const int c0 = blockIdx.y * 32;
    const int s0 = blockIdx.x * 32;
    const int tx = threadIdx.x, ty = threadIdx.y;
    const float mu = g_mu[b], rstd = g_rstd[b];

    #pragma unroll
    for (int r = 0; r < 4; r++) {
        const int cl = ty + r * 8;
        const int c  = c0 + cl;
        const int s  = s0 + tx;
        const size_t xi = ((size_t)b * CCH + c) * SS + s;   // x[b,c,s]
        const int    li = c * SS + s;                        // ln params [c,s]
        tile[cl][tx] = (x[xi] - mu) * rstd * lnw[li] + lnb[li];
    }
    __syncthreads();
    #pragma unroll
    for (int r = 0; r < 4; r++) {
        const int sl = ty + r * 8;
        // t[b, s0+sl, c0+tx]  (tx contiguous -> coalesced)
        g_t[((size_t)b * SS + (s0 + sl)) * CCH + c0 + tx] = tile[tx][sl];
    }
}

// ---------------------------------------------------------------------------
// NT SGEMM: C[m,n] = sum_k A[m,k]*Bm[n,k] (+bias) (optional relu).
// BM=BN=128, BK=8, 256 threads, 8x8 per-thread microtile, float4 throughout.
// blockIdx.z applies strides for batched (per-sample) use.
// ---------------------------------------------------------------------------
template <bool BIAS_ROW, bool RELU>
__global__ void __launch_bounds__(256, 2)
sgemm_nt_kernel(const float* __restrict__ A, const float* __restrict__ Bm,
                const float* __restrict__ bias, float* __restrict__ Cmat,
                int lda, int ldb, int ldc, int K,
                size_t aStride, size_t bStride, size_t cStride) {
    constexpr int BM = 128, BN = 128, BK = 8;
    __shared__ float As[BK][BM];
    __shared__ float Bs[BK][BN];

    A    += (size_t)blockIdx.z * aStride;
    Bm   += (size_t)blockIdx.z * bStride;
    Cmat += (size_t)blockIdx.z * cStride;

    const int tid = threadIdx.x;
    const int tx  = tid & 15;        // 0..15  -> n
    const int ty  = tid >> 4;        // 0..15  -> m
    const int m0  = blockIdx.y * BM;
    const int n0  = blockIdx.x * BN;

    const int grow = tid >> 1;           // 0..127
    const int gcol = (tid & 1) * 4;      // 0 or 4
    const float* Aptr = A  + (size_t)(m0 + grow) * lda + gcol;
    const float* Bptr = Bm + (size_t)(n0 + grow) * ldb + gcol;

    float acc[8][8];
    #pragma unroll
    for (int i = 0; i < 8; i++)
        #pragma unroll
        for (int j = 0; j < 8; j++) acc[i][j] = 0.f;

    for (int k0 = 0; k0 < K; k0 += BK) {
        float4 av = *reinterpret_cast<const float4*>(Aptr + k0);
        float4 bv = *reinterpret_cast<const float4*>(Bptr + k0);
        As[gcol + 0][grow] = av.x;
        As[gcol + 1][grow] = av.y;
        As[gcol + 2][grow] = av.z;
        As[gcol + 3][grow] = av.w;
        Bs[gcol + 0][grow] = bv.x;
        Bs[gcol + 1][grow] = bv.y;
        Bs[gcol + 2][grow] = bv.z;
        Bs[gcol + 3][grow] = bv.w;
        __syncthreads();

        #pragma unroll
        for (int kk = 0; kk < BK; kk++) {
            float4 a0 = *reinterpret_cast<const float4*>(&As[kk][ty * 8]);
            float4 a1 = *reinterpret_cast<const float4*>(&As[kk][ty * 8 + 4]);
            float4 b0 = *reinterpret_cast<const float4*>(&Bs[kk][tx * 8]);
            float4 b1 = *reinterpret_cast<const float4*>(&Bs[kk][tx * 8 + 4]);
            const float ar[8] = {a0.x, a0.y, a0.z, a0.w, a1.x, a1.y, a1.z, a1.w};
            const float br[8] = {b0.x, b0.y, b0.z, b0.w, b1.x, b1.y, b1.z, b1.w};
            #pragma unroll
            for (int i = 0; i < 8; i++)
                #pragma unroll
                for (int j = 0; j < 8; j++)
                    acc[i][j] = fmaf(ar[i], br[j], acc[i][j]);
        }
        __syncthreads();
    }

    // epilogue
    #pragma unroll
    for (int i = 0; i < 8; i++) {
        const int row = m0 + ty * 8 + i;
        const float brow = BIAS_ROW ? bias[row] : 0.f;
        #pragma unroll
        for (int j0 = 0; j0 < 8; j0 += 4) {
            float4 v;
            float* vp = &v.x;
            #pragma unroll
            for (int u = 0; u < 4; u++) {
                const int col = n0 + tx * 8 + j0 + u;
                float val = acc[i][j0 + u] + (BIAS_ROW ? brow : bias[col]);
                if (RELU) val = fmaxf(val, 0.f);
                vp[u] = val;
            }
            *reinterpret_cast<float4*>(&Cmat[(size_t)row * ldc + n0 + tx * 8 + j0]) = v;
        }
    }
}

// ---------------------------------------------------------------------------
extern "C" void kernel_launch(void* const* d_in, const int* in_sizes, int n_in,
                              void* d_out, int out_size) {
    const float* x   = (const float*)d_in[0];
    const float* lnw = (const float*)d_in[1];
    const float* lnb = (const float*)d_in[2];
    const float* w1  = (const float*)d_in[3];
    const float* b1  = (const float*)d_in[4];
    const float* w2  = (const float*)d_in[5];
    const float* b2  = (const float*)d_in[6];
    float* out = (float*)d_out;

    float* tptr = nullptr;
    float* hptr = nullptr;
    cudaGetSymbolAddress((void**)&tptr, g_t);
    cudaGetSymbolAddress((void**)&hptr, g_hdn);

    // 1) per-sample stats
    ln_stats_kernel<<<BATCH, 512>>>(x);

    // 2) normalize + transpose to tokens
    ln_apply_kernel<<<dim3(SS / 32, CCH / 32, BATCH), dim3(32, 8)>>>(x, lnw, lnb);

    // 3) GEMM1: hdn[(b,s), d] = relu( t[(b,s), :] . w1[d, :] + b1[d] )
    //    M = B*S = 131072, N = 512, K = 512. bias per column, relu.
    sgemm_nt_kernel<false, true><<<dim3(CCH / 128, (BATCH * SS) / 128, 1), 256>>>(
        tptr, w1, b1, hptr, CCH, CCH, CCH, CCH, 0, 0, 0);

    // 4) GEMM2 per sample: out_b[e, s] = w2[e, :] . hdn_b[s, :] + b2[e]
    //    M = 512 (e), N = 1024 (s), K = 512. bias per row. Output lands directly
    //    in (B, C, H, W) layout — coalesced stores.
    sgemm_nt_kernel<true, false><<<dim3(SS / 128, CCH / 128, BATCH), 256>>>(
        w2, hptr, b2, out, CCH, CCH, SS, CCH,
        0, (size_t)SS * CCH, (size_t)CCH * SS);
}

// round 3
// speedup vs baseline: 2.7137x; 2.7137x over previous
#include <cuda_runtime.h>
#include <cuda_bf16.h>
#include <cstdint>

// ---------------------------------------------------------------------------
// Problem constants
// ---------------------------------------------------------------------------
constexpr int BATCH = 128;
constexpr int CCH   = 512;    // channels
constexpr int SS    = 1024;   // H*W tokens per sample
constexpr int NPER  = CCH * SS;
constexpr float EPS = 1e-5f;

constexpr int KDIM   = 512;
constexpr int KC     = 64;            // K per chunk (128B of bf16 = one SW128 row)
constexpr int NCHUNK = KDIM / KC;     // 8
constexpr int BM = 128, BN = 128;
constexpr int THREADS = 512;

// SMEM stage layout (bytes): four 16KB arrays (128 rows x 128B, SW128)
constexpr int ST_AHI = 0;
constexpr int ST_ALO = 16384;
constexpr int ST_BHI = 32768;
constexpr int ST_BLO = 49152;
constexpr int STAGE_SZ = 65536;
constexpr int SMEM_TOTAL = 2 * STAGE_SZ;   // 128 KB dynamic

#define SW128(o) ((o) ^ (((o) >> 3) & 0x70))

// ---------------------------------------------------------------------------
// Scratch (__device__ globals)
// ---------------------------------------------------------------------------
__device__ float g_mu[BATCH];
__device__ float g_rstd[BATCH];
__device__ __nv_bfloat16 g_th[(size_t)BATCH * SS * CCH];
__device__ __nv_bfloat16 g_tl[(size_t)BATCH * SS * CCH];
__device__ __nv_bfloat16 g_hh[(size_t)BATCH * SS * CCH];
__device__ __nv_bfloat16 g_hl[(size_t)BATCH * SS * CCH];
__device__ __nv_bfloat16 g_w1h[CCH * CCH];
__device__ __nv_bfloat16 g_w1l[CCH * CCH];
__device__ __nv_bfloat16 g_w2h[CCH * CCH];
__device__ __nv_bfloat16 g_w2l[CCH * CCH];

// ---------------------------------------------------------------------------
// Small PTX wrappers (all arch-neutral: cp.async / ldmatrix / mma.sync)
// ---------------------------------------------------------------------------
__device__ __forceinline__ uint32_t smem_u32(const void* p) {
    uint32_t a;
    asm("{ .reg .u64 t; cvta.to.shared.u64 t, %1; cvt.u32.u64 %0, t; }" : "=r"(a) : "l"(p));
    return a;
}
__device__ __forceinline__ void cp_async16(uint32_t saddr, const void* g) {
    asm volatile("cp.async.cg.shared.global [%0], [%1], 16;" :: "r"(saddr), "l"(g));
}
__device__ __forceinline__ void cp_commit() { asm volatile("cp.async.commit_group;"); }
template <int N>
__device__ __forceinline__ void cp_wait() { asm volatile("cp.async.wait_group %0;" :: "n"(N)); }

__device__ __forceinline__ void ldsm4(uint32_t& r0, uint32_t& r1, uint32_t& r2, uint32_t& r3,
                                      uint32_t addr) {
    asm volatile("ldmatrix.sync.aligned.m8n8.x4.shared.b16 {%0,%1,%2,%3}, [%4];"
                 : "=r"(r0), "=r"(r1), "=r"(r2), "=r"(r3) : "r"(addr));
}
__device__ __forceinline__ void mma_bf16(float* c, const uint32_t* a, const uint32_t* b) {
    asm volatile(
        "mma.sync.aligned.m16n8k16.row.col.f32.bf16.bf16.f32 "
        "{%0,%1,%2,%3}, {%4,%5,%6,%7}, {%8,%9}, {%0,%1,%2,%3};"
        : "+f"(c[0]), "+f"(c[1]), "+f"(c[2]), "+f"(c[3])
        : "r"(a[0]), "r"(a[1]), "r"(a[2]), "r"(a[3]), "r"(b[0]), "r"(b[1]));
}

// ---------------------------------------------------------------------------
// LN stats: per-sample mean/rstd
// ---------------------------------------------------------------------------
__global__ void ln_stats_kernel(const float* __restrict__ x) {
    const int b = blockIdx.x;
    const float4* xb = reinterpret_cast<const float4*>(x + (size_t)b * NPER);
    const int n4 = NPER / 4;
    float s = 0.f, sq = 0.f;
    for (int i = threadIdx.x; i < n4; i += blockDim.x) {
        float4 v = xb[i];
        s  += v.x + v.y + v.z + v.w;
        sq += v.x * v.x + v.y * v.y + v.z * v.z + v.w * v.w;
    }
    #pragma unroll
    for (int o = 16; o > 0; o >>= 1) {
        s  += __shfl_down_sync(0xffffffffu, s,  o);
        sq += __shfl_down_sync(0xffffffffu, sq, o);
    }
    __shared__ float shs[16], shq[16];
    const int wid = threadIdx.x >> 5, lane = threadIdx.x & 31;
    if (lane == 0) { shs[wid] = s; shq[wid] = sq; }
    __syncthreads();
    if (wid == 0) {
        const int nw = blockDim.x >> 5;
        s  = (lane < nw) ? shs[lane] : 0.f;
        sq = (lane < nw) ? shq[lane] : 0.f;
        #pragma unroll
        for (int o = 8; o > 0; o >>= 1) {
            s  += __shfl_down_sync(0xffffffffu, s,  o);
            sq += __shfl_down_sync(0xffffffffu, sq, o);
        }
        if (lane == 0) {
            float mu  = s / (float)NPER;
            float var = sq / (float)NPER - mu * mu;
            g_mu[b]   = mu;
            g_rstd[b] = rsqrtf(var + EPS);
        }
    }
}

// ---------------------------------------------------------------------------
// LN apply + transpose -> bf16 hi/lo tokens (B,S,C)
// ---------------------------------------------------------------------------
__global__ void ln_apply_kernel(const float* __restrict__ x,
                                const float* __restrict__ lnw,
                                const float* __restrict__ lnb) {
    __shared__ float tile[32][33];
    const int b  = blockIdx.z;
    const int c0 = blockIdx.y * 32;
    const int s0 = blockIdx.x * 32;
    const int tx = threadIdx.x, ty = threadIdx.y;
    const float mu = g_mu[b], rstd = g_rstd[b];

    #pragma unroll
    for (int r = 0; r < 4; r++) {
        const int cl = ty + r * 8;
        const int c  = c0 + cl;
        const int s  = s0 + tx;
        const size_t xi = ((size_t)b * CCH + c) * SS + s;
        const int    li = c * SS + s;
        tile[cl][tx] = (x[xi] - mu) * rstd * lnw[li] + lnb[li];
    }
    __syncthreads();
    #pragma unroll
    for (int r = 0; r < 4; r++) {
        const int sl = ty + r * 8;
        const float v = tile[tx][sl];
        const __nv_bfloat16 h = __float2bfloat16_rn(v);
        const size_t o = ((size_t)b * SS + (s0 + sl)) * CCH + c0 + tx;
        g_th[o] = h;
        g_tl[o] = __float2bfloat16_rn(v - __bfloat162float(h));
    }
}

// ---------------------------------------------------------------------------
// fp32 -> bf16 hi/lo split (weights)
// ---------------------------------------------------------------------------
__global__ void split_kernel(const float* __restrict__ src,
                             __nv_bfloat16* __restrict__ hi,
                             __nv_bfloat16* __restrict__ lo, int n) {
    int i = blockIdx.x * blockDim.x + threadIdx.x;
    if (i < n) {
        float v = src[i];
        __nv_bfloat16 h = __float2bfloat16_rn(v);
        hi[i] = h;
        lo[i] = __float2bfloat16_rn(v - __bfloat162float(h));
    }
}

// ---------------------------------------------------------------------------
// bf16 split-GEMM via mma.sync. D[m,n] = sum_k A[m,k]*B[n,k] (3-term hi/lo).
// CTA 128x128, 512 threads, warp tile 32x32, K chunks of 64 double-buffered.
// ---------------------------------------------------------------------------
__device__ __forceinline__ void load_stage(
    const __nv_bfloat16* __restrict__ Ahi, const __nv_bfloat16* __restrict__ Alo,
    const __nv_bfloat16* __restrict__ Bhi, const __nv_bfloat16* __restrict__ Blo,
    int m0, int n0, int k0, uint32_t stage_u32, int tid)
{
    #pragma unroll
    for (int i = 0; i < 2; i++) {
        const int v = tid + i * THREADS, r = v >> 3, j = v & 7;
        cp_async16(stage_u32 + ST_AHI + SW128(r * 128 + j * 16),
                   Ahi + (size_t)(m0 + r) * KDIM + k0 + j * 8);
    }
    #pragma unroll
    for (int i = 0; i < 2; i++) {
        const int v = tid + i * THREADS, r = v >> 3, j = v & 7;
        cp_async16(stage_u32 + ST_ALO + SW128(r * 128 + j * 16),
                   Alo + (size_t)(m0 + r) * KDIM + k0 + j * 8);
    }
    #pragma unroll
    for (int i = 0; i < 2; i++) {
        const int v = tid + i * THREADS, r = v >> 3, j = v & 7;
        cp_async16(stage_u32 + ST_BHI + SW128(r * 128 + j * 16),
                   Bhi + (size_t)(n0 + r) * KDIM + k0 + j * 8);
    }
    #pragma unroll
    for (int i = 0; i < 2; i++) {
        const int v = tid + i * THREADS, r = v >> 3, j = v & 7;
        cp_async16(stage_u32 + ST_BLO + SW128(r * 128 + j * 16),
                   Blo + (size_t)(n0 + r) * KDIM + k0 + j * 8);
    }
}

template <bool GEMM1>   // GEMM1: bias per col + relu + bf16 hi/lo out. else: bias per row, fp32 out.
__global__ void __launch_bounds__(THREADS, 1)
gemm_mma(const __nv_bfloat16* __restrict__ Ahi, const __nv_bfloat16* __restrict__ Alo,
         const __nv_bfloat16* __restrict__ Bhi, const __nv_bfloat16* __restrict__ Blo,
         const float* __restrict__ bias,
         float* __restrict__ outF,
         __nv_bfloat16* __restrict__ outHi, __nv_bfloat16* __restrict__ outLo,
         size_t bZ, size_t outZ, int ldOut)
{
    extern __shared__ __align__(1024) char smem[];
    const uint32_t sbase = smem_u32(smem);
    const int tid  = threadIdx.x;
    const int w    = tid >> 5;
    const int lane = tid & 31;
    const int m0   = blockIdx.y * BM;
    const int n0   = blockIdx.x * BN;
    const size_t z = blockIdx.z;
    Bhi += z * bZ;
    Blo += z * bZ;

    const int warpM = (w & 3) * 32;
    const int warpN = (w >> 2) * 32;

    // per-lane ldmatrix row/col constants
    const int rA = (lane & 7) + ((lane >> 3) & 1) * 8;   // A: lanes 0-7 m0-7@k0, 8-15 m8-15@k0, 16-23 m0-7@k8, 24-31 m8-15@k8
    const int kA = (lane >> 4) * 16;                     // byte offset (k8 -> +16B)
    const int rB = (lane & 7) + ((lane >> 4) & 1) * 8;   // B: 0-7 n0-7@k0, 8-15 n0-7@k8, 16-23 n8-15@k0, 24-31 n8-15@k8
    const int kB = ((lane >> 3) & 1) * 16;

    float acc[2][4][4];
    #pragma unroll
    for (int mt = 0; mt < 2; mt++)
        #pragma unroll
        for (int nt = 0; nt < 4; nt++)
            #pragma unroll
            for (int r = 0; r < 4; r++) acc[mt][nt][r] = 0.f;

    load_stage(Ahi, Alo, Bhi, Blo, m0, n0, 0, sbase, tid);
    cp_commit();

    for (int k = 0; k < NCHUNK; k++) {
        const uint32_t st = sbase + (k & 1) * STAGE_SZ;
        if (k + 1 < NCHUNK) {
            load_stage(Ahi, Alo, Bhi, Blo, m0, n0, (k + 1) * KC,
                       sbase + ((k + 1) & 1) * STAGE_SZ, tid);
            cp_commit();
            cp_wait<1>();
        } else {
            cp_wait<0>();
        }
        __syncthreads();

        #pragma unroll
        for (int ks = 0; ks < 4; ks++) {
            uint32_t ah[2][4], al[2][4], bh[2][4], bl[2][4];
            #pragma unroll
            for (int mt = 0; mt < 2; mt++) {
                const int off = SW128((warpM + mt * 16 + rA) * 128 + ks * 32 + kA);
                ldsm4(ah[mt][0], ah[mt][1], ah[mt][2], ah[mt][3], st + ST_AHI + off);
                ldsm4(al[mt][0], al[mt][1], al[mt][2], al[mt][3], st + ST_ALO + off);
            }
            #pragma unroll
            for (int np = 0; np < 2; np++) {
                const int off = SW128((warpN + np * 16 + rB) * 128 + ks * 32 + kB);
                ldsm4(bh[np][0], bh[np][1], bh[np][2], bh[np][3], st + ST_BHI + off);
                ldsm4(bl[np][0], bl[np][1], bl[np][2], bl[np][3], st + ST_BLO + off);
            }
            #pragma unroll
            for (int mt = 0; mt < 2; mt++)
                #pragma unroll
                for (int nt = 0; nt < 4; nt++) {
                    const uint32_t* bhp = &bh[nt >> 1][(nt & 1) * 2];
                    const uint32_t* blp = &bl[nt >> 1][(nt & 1) * 2];
                    mma_bf16(acc[mt][nt], ah[mt], bhp);   // hi*hi
                    mma_bf16(acc[mt][nt], ah[mt], blp);   // hi*lo
                    mma_bf16(acc[mt][nt], al[mt], bhp);   // lo*hi
                }
        }
        __syncthreads();
    }

    // ---------------- epilogue ----------------
    const int g    = lane >> 2;          // row within 8-row group
    const int c0l  = (lane & 3) * 2;     // col pair within n8 tile
    if (GEMM1) {
        #pragma unroll
        for (int mt = 0; mt < 2; mt++) {
            #pragma unroll
            for (int nt = 0; nt < 4; nt++) {
                const int col = n0 + warpN + nt * 8 + c0l;
                const float2 bv = *reinterpret_cast<const float2*>(bias + col);
                #pragma unroll
                for (int half = 0; half < 2; half++) {
                    const int row = m0 + warpM + mt * 16 + g + half * 8;
                    float v0 = fmaxf(acc[mt][nt][half * 2 + 0] + bv.x, 0.f);
                    float v1 = fmaxf(acc[mt][nt][half * 2 + 1] + bv.y, 0.f);
                    const __nv_bfloat16 h0 = __float2bfloat16_rn(v0);
                    const __nv_bfloat16 h1 = __float2bfloat16_rn(v1);
                    const __nv_bfloat16 l0 = __float2bfloat16_rn(v0 - __bfloat162float(h0));
                    const __nv_bfloat16 l1 = __float2bfloat16_rn(v1 - __bfloat162float(h1));
                    const size_t o = (size_t)row * ldOut + col;
                    *reinterpret_cast<__nv_bfloat162*>(outHi + o) = __nv_bfloat162(h0, h1);
                    *reinterpret_cast<__nv_bfloat162*>(outLo + o) = __nv_bfloat162(l0, l1);
                }
            }
        }
    } else {
        float* outZp = outF + z * outZ;
        #pragma unroll
        for (int mt = 0; mt < 2; mt++) {
            #pragma unroll
            for (int half = 0; half < 2; half++) {
                const int row = m0 + warpM + mt * 16 + g + half * 8;
                const float bm = bias[row];
                #pragma unroll
                for (int nt = 0; nt < 4; nt++) {
                    const int col = n0 + warpN + nt * 8 + c0l;
                    float2 v;
                    v.x = acc[mt][nt][half * 2 + 0] + bm;
                    v.y = acc[mt][nt][half * 2 + 1] + bm;
                    *reinterpret_cast<float2*>(outZp + (size_t)row * ldOut + col) = v;
                }
            }
        }
    }
}

// ---------------------------------------------------------------------------
extern "C" void kernel_launch(void* const* d_in, const int* in_sizes, int n_in,
                              void* d_out, int out_size) {
    const float* x   = (const float*)d_in[0];
    const float* lnw = (const float*)d_in[1];
    const float* lnb = (const float*)d_in[2];
    const float* w1  = (const float*)d_in[3];
    const float* b1  = (const float*)d_in[4];
    const float* w2  = (const float*)d_in[5];
    const float* b2  = (const float*)d_in[6];
    float* out = (float*)d_out;

    __nv_bfloat16 *th, *tl, *hh, *hl, *w1h, *w1l, *w2h, *w2l;
    cudaGetSymbolAddress((void**)&th,  g_th);
    cudaGetSymbolAddress((void**)&tl,  g_tl);
    cudaGetSymbolAddress((void**)&hh,  g_hh);
    cudaGetSymbolAddress((void**)&hl,  g_hl);
    cudaGetSymbolAddress((void**)&w1h, g_w1h);
    cudaGetSymbolAddress((void**)&w1l, g_w1l);
    cudaGetSymbolAddress((void**)&w2h, g_w2h);
    cudaGetSymbolAddress((void**)&w2l, g_w2l);

    cudaFuncSetAttribute(gemm_mma<true>,
                         cudaFuncAttributeMaxDynamicSharedMemorySize, SMEM_TOTAL);
    cudaFuncSetAttribute(gemm_mma<false>,
                         cudaFuncAttributeMaxDynamicSharedMemorySize, SMEM_TOTAL);

    // 0) weight hi/lo splits
    split_kernel<<<(CCH * CCH + 255) / 256, 256>>>(w1, w1h, w1l, CCH * CCH);
    split_kernel<<<(CCH * CCH + 255) / 256, 256>>>(w2, w2h, w2l, CCH * CCH);

    // 1) per-sample LN stats
    ln_stats_kernel<<<BATCH, 512>>>(x);

    // 2) normalize + transpose -> bf16 hi/lo tokens (B,S,C)
    ln_apply_kernel<<<dim3(SS / 32, CCH / 32, BATCH), dim3(32, 8)>>>(x, lnw, lnb);

    // 3) GEMM1: hdn[tok, d] = relu(t[tok,:].w1[d,:] + b1[d]); M=131072, N=512
    gemm_mma<true><<<dim3(CCH / BN, (BATCH * SS) / BM, 1), THREADS, SMEM_TOTAL>>>(
        th, tl, w1h, w1l, b1, nullptr, hh, hl, 0, 0, CCH);

    // 4) GEMM2 per sample: out_b[e, s] = w2[e,:].hdn_b[s,:] + b2[e]; M=512, N=1024
    gemm_mma<false><<<dim3(SS / BN, CCH / BM, BATCH), THREADS, SMEM_TOTAL>>>(
        w2h, w2l, hh, hl, b2, out, nullptr, nullptr,
        (size_t)SS * CCH, (size_t)CCH * SS, SS);
}

// round 7
// speedup vs baseline: 2.8929x; 1.0660x over previous
#include <cuda_runtime.h>
#include <cuda_bf16.h>
#include <cstdint>

// ---------------------------------------------------------------------------
// Problem constants
// ---------------------------------------------------------------------------
constexpr int BATCH = 128;
constexpr int CCH   = 512;
constexpr int SS    = 1024;
constexpr int NPER  = CCH * SS;
constexpr float EPS = 1e-5f;

constexpr int KDIM   = 512;
constexpr int KC     = 64;            // K per chunk (128B row of bf16, SW128)
constexpr int NCHUNK = KDIM / KC;     // 8
constexpr int BM = 128, BN = 256;     // CTA tile
constexpr int THREADS = 256;          // 8 warps, each 64x64

// SMEM stage layout (bytes)
constexpr int ST_AHI = 0;                 // 128 rows x 128B
constexpr int ST_ALO = 16384;
constexpr int ST_BHI = 32768;             // 256 rows x 128B
constexpr int ST_BLO = 65536;
constexpr int STAGE_SZ = 98304;           // 96 KB
constexpr int SMEM_TOTAL = 2 * STAGE_SZ;  // 192 KB

#define SW128(o) ((o) ^ (((o) >> 3) & 0x70))

// ---------------------------------------------------------------------------
// Scratch
// ---------------------------------------------------------------------------
__device__ float g_mu[BATCH];
__device__ float g_rstd[BATCH];
__device__ __nv_bfloat16 g_th[(size_t)BATCH * SS * CCH];
__device__ __nv_bfloat16 g_tl[(size_t)BATCH * SS * CCH];
__device__ __nv_bfloat16 g_hh[(size_t)BATCH * SS * CCH];
__device__ __nv_bfloat16 g_hl[(size_t)BATCH * SS * CCH];
__device__ __nv_bfloat16 g_w1h[CCH * CCH];
__device__ __nv_bfloat16 g_w1l[CCH * CCH];
__device__ __nv_bfloat16 g_w2h[CCH * CCH];
__device__ __nv_bfloat16 g_w2l[CCH * CCH];

// ---------------------------------------------------------------------------
// PTX wrappers (arch-neutral)
// ---------------------------------------------------------------------------
__device__ __forceinline__ uint32_t smem_u32(const void* p) {
    uint32_t a;
    asm("{ .reg .u64 t; cvta.to.shared.u64 t, %1; cvt.u32.u64 %0, t; }" : "=r"(a) : "l"(p));
    return a;
}
__device__ __forceinline__ void cp_async16(uint32_t saddr, const void* g) {
    asm volatile("cp.async.cg.shared.global [%0], [%1], 16;" :: "r"(saddr), "l"(g));
}
__device__ __forceinline__ void cp_commit() { asm volatile("cp.async.commit_group;"); }
template <int N>
__device__ __forceinline__ void cp_wait() { asm volatile("cp.async.wait_group %0;" :: "n"(N)); }

__device__ __forceinline__ void ldsm4(uint32_t& r0, uint32_t& r1, uint32_t& r2, uint32_t& r3,
                                      uint32_t addr) {
    asm volatile("ldmatrix.sync.aligned.m8n8.x4.shared.b16 {%0,%1,%2,%3}, [%4];"
                 : "=r"(r0), "=r"(r1), "=r"(r2), "=r"(r3) : "r"(addr));
}
__device__ __forceinline__ void mma_bf16(float* c, const uint32_t* a, const uint32_t* b) {
    asm volatile(
        "mma.sync.aligned.m16n8k16.row.col.f32.bf16.bf16.f32 "
        "{%0,%1,%2,%3}, {%4,%5,%6,%7}, {%8,%9}, {%0,%1,%2,%3};"
        : "+f"(c[0]), "+f"(c[1]), "+f"(c[2]), "+f"(c[3])
        : "r"(a[0]), "r"(a[1]), "r"(a[2]), "r"(a[3]), "r"(b[0]), "r"(b[1]));
}

// ---------------------------------------------------------------------------
// LN stats
// ---------------------------------------------------------------------------
__global__ void ln_stats_kernel(const float* __restrict__ x) {
    const int b = blockIdx.x;
    const float4* xb = reinterpret_cast<const float4*>(x + (size_t)b * NPER);
    const int n4 = NPER / 4;
    float s = 0.f, sq = 0.f;
    for (int i = threadIdx.x; i < n4; i += blockDim.x) {
        float4 v = xb[i];
        s  += v.x + v.y + v.z + v.w;
        sq += v.x * v.x + v.y * v.y + v.z * v.z + v.w * v.w;
    }
    #pragma unroll
    for (int o = 16; o > 0; o >>= 1) {
        s  += __shfl_down_sync(0xffffffffu, s,  o);
        sq += __shfl_down_sync(0xffffffffu, sq, o);
    }
    __shared__ float shs[16], shq[16];
    const int wid = threadIdx.x >> 5, lane = threadIdx.x & 31;
    if (lane == 0) { shs[wid] = s; shq[wid] = sq; }
    __syncthreads();
    if (wid == 0) {
        const int nw = blockDim.x >> 5;
        s  = (lane < nw) ? shs[lane] : 0.f;
        sq = (lane < nw) ? shq[lane] : 0.f;
        #pragma unroll
        for (int o = 8; o > 0; o >>= 1) {
            s  += __shfl_down_sync(0xffffffffu, s,  o);
            sq += __shfl_down_sync(0xffffffffu, sq, o);
        }
        if (lane == 0) {
            float mu  = s / (float)NPER;
            float var = sq / (float)NPER - mu * mu;
            g_mu[b]   = mu;
            g_rstd[b] = rsqrtf(var + EPS);
        }
    }
}

// ---------------------------------------------------------------------------
// LN apply + transpose -> bf16 hi/lo tokens (B,S,C); paired bf16x2 stores.
// tile: 32 s x 64 c. grid=(S/32, C/64, B), block=(32,8).
// ---------------------------------------------------------------------------
__global__ void ln_apply_kernel(const float* __restrict__ x,
                                const float* __restrict__ lnw,
                                const float* __restrict__ lnb) {
    __shared__ float tile[32][65];      // [s][c], padded
    const int b  = blockIdx.z;
    const int c0 = blockIdx.y * 64;
    const int s0 = blockIdx.x * 32;
    const int tx = threadIdx.x, ty = threadIdx.y;
    const float mu = g_mu[b], rstd = g_rstd[b];

    #pragma unroll
    for (int r = 0; r < 8; r++) {
        const int cl = ty + r * 8;          // 0..63
        const int c  = c0 + cl;
        const int s  = s0 + tx;
        const size_t xi = ((size_t)b * CCH + c) * SS + s;
        const int    li = c * SS + s;
        tile[tx][cl] = (x[xi] - mu) * rstd * lnw[li] + lnb[li];
    }
    __syncthreads();
    #pragma unroll
    for (int r = 0; r < 4; r++) {
        const int sl = ty + r * 8;          // 0..31
        const float v0 = tile[sl][tx * 2 + 0];
        const float v1 = tile[sl][tx * 2 + 1];
        const __nv_bfloat16 h0 = __float2bfloat16_rn(v0);
        const __nv_bfloat16 h1 = __float2bfloat16_rn(v1);
        const __nv_bfloat16 l0 = __float2bfloat16_rn(v0 - __bfloat162float(h0));
        const __nv_bfloat16 l1 = __float2bfloat16_rn(v1 - __bfloat162float(h1));
        const size_t o = ((size_t)b * SS + (s0 + sl)) * CCH + c0 + tx * 2;
        *reinterpret_cast<__nv_bfloat162*>(g_th + o) = __nv_bfloat162(h0, h1);
        *reinterpret_cast<__nv_bfloat162*>(g_tl + o) = __nv_bfloat162(l0, l1);
    }
}

// ---------------------------------------------------------------------------
// fp32 -> bf16 hi/lo split (weights)
// ---------------------------------------------------------------------------
__global__ void split_kernel(const float* __restrict__ src,
                             __nv_bfloat16* __restrict__ hi,
                             __nv_bfloat16* __restrict__ lo, int n) {
    int i = blockIdx.x * blockDim.x + threadIdx.x;
    if (i < n) {
        float v = src[i];
        __nv_bfloat16 h = __float2bfloat16_rn(v);
        hi[i] = h;
        lo[i] = __float2bfloat16_rn(v - __bfloat162float(h));
    }
}

// ---------------------------------------------------------------------------
// Split-GEMM: CTA 128x256, 8 warps of 64x64, KC=64 double-buffered.
// ---------------------------------------------------------------------------
__device__ __forceinline__ void load_stage(
    const __nv_bfloat16* __restrict__ Ahi, const __nv_bfloat16* __restrict__ Alo,
    const __nv_bfloat16* __restrict__ Bhi, const __nv_bfloat16* __restrict__ Blo,
    int m0, int n0, int k0, uint32_t stage_u32, int tid)
{
    #pragma unroll
    for (int i = 0; i < 4; i++) {                 // A: 128 rows x 8 chunks = 1024
        const int v = tid + i * THREADS, r = v >> 3, j = v & 7;
        cp_async16(stage_u32 + ST_AHI + SW128(r * 128 + j * 16),
                   Ahi + (size_t)(m0 + r) * KDIM + k0 + j * 8);
    }
    #pragma unroll
    for (int i = 0; i < 4; i++) {
        const int v = tid + i * THREADS, r = v >> 3, j = v & 7;
        cp_async16(stage_u32 + ST_ALO + SW128(r * 128 + j * 16),
                   Alo + (size_t)(m0 + r) * KDIM + k0 + j * 8);
    }
    #pragma unroll
    for (int i = 0; i < 8; i++) {                 // B: 256 rows x 8 = 2048
        const int v = tid + i * THREADS, r = v >> 3, j = v & 7;
        cp_async16(stage_u32 + ST_BHI + SW128(r * 128 + j * 16),
                   Bhi + (size_t)(n0 + r) * KDIM + k0 + j * 8);
    }
    #pragma unroll
    for (int i = 0; i < 8; i++) {
        const int v = tid + i * THREADS, r = v >> 3, j = v & 7;
        cp_async16(stage_u32 + ST_BLO + SW128(r * 128 + j * 16),
                   Blo + (size_t)(n0 + r) * KDIM + k0 + j * 8);
    }
}

template <bool GEMM1>
__global__ void __launch_bounds__(THREADS, 1)
gemm_mma(const __nv_bfloat16* __restrict__ Ahi, const __nv_bfloat16* __restrict__ Alo,
         const __nv_bfloat16* __restrict__ Bhi, const __nv_bfloat16* __restrict__ Blo,
         const float* __restrict__ bias,
         float* __restrict__ outF,
         __nv_bfloat16* __restrict__ outHi, __nv_bfloat16* __restrict__ outLo,
         size_t bZ, size_t outZ, int ldOut)
{
    extern __shared__ __align__(1024) char smem[];
    const uint32_t sbase = smem_u32(smem);
    const int tid  = threadIdx.x;
    const int w    = tid >> 5;
    const int lane = tid & 31;
    const int m0   = blockIdx.y * BM;
    const int n0   = blockIdx.x * BN;
    const size_t z = blockIdx.z;
    Bhi += z * bZ;
    Blo += z * bZ;

    const int warpM = (w & 1) * 64;     // 2 x 4 warp grid of 64x64 tiles
    const int warpN = (w >> 1) * 64;

    const int rA = (lane & 7) + ((lane >> 3) & 1) * 8;
    const int kA = (lane >> 4) * 16;
    const int rB = (lane & 7) + ((lane >> 4) & 1) * 8;
    const int kB = ((lane >> 3) & 1) * 16;

    float acc[4][8][4];                 // [mt][n8][4]
    #pragma unroll
    for (int mt = 0; mt < 4; mt++)
        #pragma unroll
        for (int nt = 0; nt < 8; nt++)
            #pragma unroll
            for (int r = 0; r < 4; r++) acc[mt][nt][r] = 0.f;

    load_stage(Ahi, Alo, Bhi, Blo, m0, n0, 0, sbase, tid);
    cp_commit();

    for (int k = 0; k < NCHUNK; k++) {
        const uint32_t st = sbase + (k & 1) * STAGE_SZ;
        if (k + 1 < NCHUNK) {
            load_stage(Ahi, Alo, Bhi, Blo, m0, n0, (k + 1) * KC,
                       sbase + ((k + 1) & 1) * STAGE_SZ, tid);
            cp_commit();
            cp_wait<1>();
        } else {
            cp_wait<0>();
        }
        __syncthreads();

        #pragma unroll
        for (int ks = 0; ks < 4; ks++) {
            uint32_t ah[4][4], al[4][4];
            #pragma unroll
            for (int mt = 0; mt < 4; mt++) {
                const int off = SW128((warpM + mt * 16 + rA) * 128 + ks * 32 + kA);
                ldsm4(ah[mt][0], ah[mt][1], ah[mt][2], ah[mt][3], st + ST_AHI + off);
                ldsm4(al[mt][0], al[mt][1], al[mt][2], al[mt][3], st + ST_ALO + off);
            }
            #pragma unroll
            for (int np = 0; np < 4; np++) {        // 4 x 16-col groups
                uint32_t bh[4], bl[4];
                const int off = SW128((warpN + np * 16 + rB) * 128 + ks * 32 + kB);
                ldsm4(bh[0], bh[1], bh[2], bh[3], st + ST_BHI + off);
                ldsm4(bl[0], bl[1], bl[2], bl[3], st + ST_BLO + off);
                #pragma unroll
                for (int mt = 0; mt < 4; mt++)
                    #pragma unroll
                    for (int half = 0; half < 2; half++) {
                        float* a = acc[mt][np * 2 + half];
                        mma_bf16(a, ah[mt], &bh[half * 2]);   // hi*hi
                        mma_bf16(a, ah[mt], &bl[half * 2]);   // hi*lo
                        mma_bf16(a, al[mt], &bh[half * 2]);   // lo*hi
                    }
            }
        }
        __syncthreads();
    }

    // ---------------- epilogue ----------------
    const int g   = lane >> 2;
    const int c0l = (lane & 3) * 2;
    if (GEMM1) {
        #pragma unroll
        for (int mt = 0; mt < 4; mt++) {
            #pragma unroll
            for (int nt = 0; nt < 8; nt++) {
                const int col = n0 + warpN + nt * 8 + c0l;
                const float2 bv = *reinterpret_cast<const float2*>(bias + col);
                #pragma unroll
                for (int half = 0; half < 2; half++) {
                    const int row = m0 + warpM + mt * 16 + g + half * 8;
                    float v0 = fmaxf(acc[mt][nt][half * 2 + 0] + bv.x, 0.f);
                    float v1 = fmaxf(acc[mt][nt][half * 2 + 1] + bv.y, 0.f);
                    const __nv_bfloat16 h0 = __float2bfloat16_rn(v0);
                    const __nv_bfloat16 h1 = __float2bfloat16_rn(v1);
                    const __nv_bfloat16 l0 = __float2bfloat16_rn(v0 - __bfloat162float(h0));
                    const __nv_bfloat16 l1 = __float2bfloat16_rn(v1 - __bfloat162float(h1));
                    const size_t o = (size_t)row * ldOut + col;
                    *reinterpret_cast<__nv_bfloat162*>(outHi + o) = __nv_bfloat162(h0, h1);
                    *reinterpret_cast<__nv_bfloat162*>(outLo + o) = __nv_bfloat162(l0, l1);
                }
            }
        }
    } else {
        float* outZp = outF + z * outZ;
        #pragma unroll
        for (int mt = 0; mt < 4; mt++) {
            #pragma unroll
            for (int half = 0; half < 2; half++) {
                const int row = m0 + warpM + mt * 16 + g + half * 8;
                const float bm = bias[row];
                #pragma unroll
                for (int nt = 0; nt < 8; nt++) {
                    const int col = n0 + warpN + nt * 8 + c0l;
                    float2 v;
                    v.x = acc[mt][nt][half * 2 + 0] + bm;
                    v.y = acc[mt][nt][half * 2 + 1] + bm;
                    *reinterpret_cast<float2*>(outZp + (size_t)row * ldOut + col) = v;
                }
            }
        }
    }
}

// ---------------------------------------------------------------------------
extern "C" void kernel_launch(void* const* d_in, const int* in_sizes, int n_in,
                              void* d_out, int out_size) {
    const float* x   = (const float*)d_in[0];
    const float* lnw = (const float*)d_in[1];
    const float* lnb = (const float*)d_in[2];
    const float* w1  = (const float*)d_in[3];
    const float* b1  = (const float*)d_in[4];
    const float* w2  = (const float*)d_in[5];
    const float* b2  = (const float*)d_in[6];
    float* out = (float*)d_out;

    __nv_bfloat16 *th, *tl, *hh, *hl, *w1h, *w1l, *w2h, *w2l;
    cudaGetSymbolAddress((void**)&th,  g_th);
    cudaGetSymbolAddress((void**)&tl,  g_tl);
    cudaGetSymbolAddress((void**)&hh,  g_hh);
    cudaGetSymbolAddress((void**)&hl,  g_hl);
    cudaGetSymbolAddress((void**)&w1h, g_w1h);
    cudaGetSymbolAddress((void**)&w1l, g_w1l);
    cudaGetSymbolAddress((void**)&w2h, g_w2h);
    cudaGetSymbolAddress((void**)&w2l, g_w2l);

    cudaFuncSetAttribute(gemm_mma<true>,
                         cudaFuncAttributeMaxDynamicSharedMemorySize, SMEM_TOTAL);
    cudaFuncSetAttribute(gemm_mma<false>,
                         cudaFuncAttributeMaxDynamicSharedMemorySize, SMEM_TOTAL);

    split_kernel<<<(CCH * CCH + 255) / 256, 256>>>(w1, w1h, w1l, CCH * CCH);
    split_kernel<<<(CCH * CCH + 255) / 256, 256>>>(w2, w2h, w2l, CCH * CCH);

    ln_stats_kernel<<<BATCH, 512>>>(x);
    ln_apply_kernel<<<dim3(SS / 32, CCH / 64, BATCH), dim3(32, 8)>>>(x, lnw, lnb);

    // GEMM1: hdn[tok, d] = relu(t.w1^T + b1); M=131072, N=512, K=512
    gemm_mma<true><<<dim3(CCH / BN, (BATCH * SS) / BM, 1), THREADS, SMEM_TOTAL>>>(
        th, tl, w1h, w1l, b1, nullptr, hh, hl, 0, 0, CCH);

    // GEMM2 per sample: out_b[e, s] = w2[e,:].hdn_b[s,:] + b2[e]; M=512, N=1024
    gemm_mma<false><<<dim3(SS / BN, CCH / BM, BATCH), THREADS, SMEM_TOTAL>>>(
        w2h, w2l, hh, hl, b2, out, nullptr, nullptr,
        (size_t)SS * CCH, (size_t)CCH * SS, SS);
}